// round 15
// baseline (speedup 1.0000x reference)
#include <cuda_runtime.h>

// out[b, p*64+m] = x[b,m]*(w[p,0]-w[p,1]) + S[b]*w[p,1],  S[b]=sum_n x[b,n]
// indices = 1 - eye(64)  => closed form; indices input unused.
//
// Final-form kernel, occupancy-maximized. HBM-write-bound at the measured
// device ceiling (~5.4-5.8 TB/s for this 9:1 write:read fp32 stream).
// Verified neutral-or-worse across rounds: extra MLP, TMA bulk stores,
// cache policies, read/write de-mixing, 256-bit ops, store segment shape.
//
// Persistent warps, one row per warp iteration, whole-warp 2KB row bursts.
// Weight tables preselected per lane (hi = lane>>4 picks p parity), so only
// 8 weight registers live -> fits 8 blocks/SM (100% occupancy).
__global__ void __launch_bounds__(256, 8)
perm_closed_kernel(const float4* __restrict__ x4,
                   const float* __restrict__ w,
                   float4* __restrict__ out4,
                   int nrows)
{
    int lane = threadIdx.x & 31;
    int sub  = lane & 15;          // float4 slot of the x row
    int hi   = lane >> 4;          // p parity for this lane

    // Preselect this lane's 4 (A, S-coeff) pairs: p = 2k + hi, k=0..3.
    // w layout: w[p*2] = diag coeff w0, w[p*2+1] = off-diag w1.
    float A[4], sw[4];
    #pragma unroll
    for (int k = 0; k < 4; k++) {
        int p = 2 * k + hi;
        float w0 = __ldg(&w[2 * p]);
        float w1 = __ldg(&w[2 * p + 1]);
        A[k]  = w0 - w1;
        sw[k] = w1;
    }

    int warpsTotal = (int)((gridDim.x * blockDim.x) >> 5);
    int warpId     = (int)((blockIdx.x * blockDim.x + threadIdx.x) >> 5);

    const float4* __restrict__ xp = x4   + (size_t)warpId * 16  + sub;
    float4*       __restrict__ op = out4 + (size_t)warpId * 128 + lane;
    const size_t xstep = (size_t)warpsTotal * 16;
    const size_t ostep = (size_t)warpsTotal * 128;

    for (int row = warpId; row < nrows;
         row += warpsTotal, xp += xstep, op += ostep) {
        float4 xv = __ldcs(xp);    // lanes 16..31 broadcast-duplicate 0..15

        // Row sum: halves hold identical data; butterfly 8,4,2,1 reduces
        // each half; every lane ends with the full row sum S.
        float s = (xv.x + xv.y) + (xv.z + xv.w);
        #pragma unroll
        for (int off = 8; off > 0; off >>= 1)
            s += __shfl_xor_sync(0xffffffffu, s, off);

        #pragma unroll
        for (int k = 0; k < 4; k++) {
            float sc = s * sw[k];
            float4 r;
            r.x = fmaf(xv.x, A[k], sc);
            r.y = fmaf(xv.y, A[k], sc);
            r.z = fmaf(xv.z, A[k], sc);
            r.w = fmaf(xv.w, A[k], sc);
            __stcs(op + 32 * k, r);   // full-warp contiguous 512B burst
        }
    }
}

extern "C" void kernel_launch(void* const* d_in, const int* in_sizes, int n_in,
                              void* d_out, int out_size)
{
    const float* x = (const float*)d_in[0];   // (B, 64) fp32
    const float* w = (const float*)d_in[1];   // (8, 2) fp32
    // d_in[2] = indices (unused: 1 - eye closed form)

    int nrows = in_sizes[0] / 64;             // B = 262144

    // 8 blocks/SM x 152 SMs = 1216 blocks, full single-wave residency.
    perm_closed_kernel<<<1216, 256>>>(
        (const float4*)x, w, (float4*)d_out, nrows);
}

// round 16
// speedup vs baseline: 1.1771x; 1.1771x over previous
#include <cuda_runtime.h>

// out[b, p*64+m] = x[b,m]*(w[p,0]-w[p,1]) + S[b]*w[p,1],  S[b]=sum_n x[b,n]
// indices = 1 - eye(64)  => closed form; indices input unused.
//
// Final kernel. HBM-write-bound at the measured device ceiling (~5.5 TB/s
// effective for this 9:1 write:read fp32 stream). Non-persistent layout:
// concurrently-resident warps own ADJACENT rows, so the in-flight write
// streams are spatially contiguous (best DRAM page locality — this layout
// produced the best measured wall time).
//
// One warp per row. Lane j loads xrow4[j & 15] (lanes 16..31 duplicate via
// L1 broadcast); butterfly 8,4,2,1 gives all lanes the row sum; 4 STG.128
// per lane form one contiguous 2KB burst per warp covering the output row.
// Per-lane weight preselect (p = 2k + (lane>>4)) keeps regs ~26.
__global__ void __launch_bounds__(256, 8)
perm_closed_kernel(const float4* __restrict__ x4,
                   const float* __restrict__ w,
                   float4* __restrict__ out4,
                   int nrows)
{
    int warp = (int)((blockIdx.x * (unsigned)blockDim.x + threadIdx.x) >> 5);
    int lane = threadIdx.x & 31;
    if (warp >= nrows) return;

    int sub = lane & 15;
    int hi  = lane >> 4;

    // Preselect this lane's 4 (A, S-coeff) pairs: p = 2k + hi.
    float A[4], sw[4];
    #pragma unroll
    for (int k = 0; k < 4; k++) {
        int p = 2 * k + hi;
        float w0 = __ldg(&w[2 * p]);
        float w1 = __ldg(&w[2 * p + 1]);
        A[k]  = w0 - w1;
        sw[k] = w1;
    }

    float4 xv = __ldcs(x4 + (size_t)warp * 16 + sub);

    // Row sum: halves duplicate; butterfly reduces each half identically.
    float s = (xv.x + xv.y) + (xv.z + xv.w);
    #pragma unroll
    for (int off = 8; off > 0; off >>= 1)
        s += __shfl_xor_sync(0xffffffffu, s, off);

    float4* __restrict__ op = out4 + (size_t)warp * 128 + lane;
    #pragma unroll
    for (int k = 0; k < 4; k++) {
        float sc = s * sw[k];
        float4 r;
        r.x = fmaf(xv.x, A[k], sc);
        r.y = fmaf(xv.y, A[k], sc);
        r.z = fmaf(xv.z, A[k], sc);
        r.w = fmaf(xv.w, A[k], sc);
        __stcs(op + 32 * k, r);   // whole-warp contiguous 512B burst
    }
}

extern "C" void kernel_launch(void* const* d_in, const int* in_sizes, int n_in,
                              void* d_out, int out_size)
{
    const float* x = (const float*)d_in[0];   // (B, 64) fp32
    const float* w = (const float*)d_in[1];   // (8, 2) fp32
    // d_in[2] = indices (unused: 1 - eye closed form)

    int nrows  = in_sizes[0] / 64;            // B = 262144
    int blocks = (nrows + 7) / 8;             // 8 warps (rows) per block

    perm_closed_kernel<<<blocks, 256>>>(
        (const float4*)x, w, (float4*)d_out, nrows);
}